// round 16
// baseline (speedup 1.0000x reference)
#include <cuda_runtime.h>
#include <cuda_fp16.h>
#include <math.h>

#define Bc 2
#define Vc 5
#define Cc 32
#define Hc 128
#define Wc 160
#define Dc 32
#define Gc 8
#define HWc (Hc*Wc)            // 20480
#define BHW (Bc*HWc)           // 40960
#define BDHW (Bc*Dc*HWc)       // 1310720

// ---------------- scratch (device globals) ----------------
__device__ uint4   g_simh4[(size_t)(Vc-1)*Bc*Dc*HWc];    // sim: 8 half per voxel
__device__ float   g_feat[(size_t)Bc*Cc*HWc];            // view-0 fp32 (B,G,HW,4)
__device__ uint4   g_feath[(size_t)Vc*Bc*4*HWc];         // all views half (VB,4pl,HW)
__device__ float   g_c1[(size_t)Bc*8*Dc*HWc];            // conv1 output
__device__ float   g_proj[(Vc-1)*Bc][16];                // R(9)+t(3)+fastflag
__device__ float   g_td[(Vc-1)*Bc][Dc];                  // t_d = P9/dep_d
__device__ float   g_S[4];                               // S, b3, flag
__device__ float   g_dvb[1];                             // dv-broadcast flag

// ---------------- helpers ----------------
__device__ __forceinline__ unsigned long long pk2(float lo, float hi) {
    unsigned long long r;
    asm("mov.b64 %0, {%1,%2};" : "=l"(r) : "f"(lo), "f"(hi));
    return r;
}
__device__ __forceinline__ void fma2(unsigned long long& d,
                                     unsigned long long a, unsigned long long b) {
    asm("fma.rn.f32x2 %0, %1, %2, %0;" : "+l"(d) : "l"(a), "l"(b));
}
__device__ __forceinline__ float2 upk2(unsigned long long v) {
    float2 r;
    asm("mov.b64 {%0,%1}, %2;" : "=f"(r.x), "=f"(r.y) : "l"(v));
    return r;
}
__device__ __forceinline__ __half2 u2h(unsigned int u) { return *(__half2*)&u; }
__device__ __forceinline__ float ex2f(float x) {
    float r;
    asm("ex2.approx.f32 %0, %1;" : "=f"(r) : "f"(x));
    return r;
}

// ---------------- projection + MLP-fold setup ----------------
__device__ void combine_mat(const float* pm, double out[16]) {
    const float* e = pm;
    const float* K = pm + 16;
    for (int r = 0; r < 4; r++)
        for (int c = 0; c < 4; c++)
            out[r*4+c] = (double)e[r*4+c];
    for (int r = 0; r < 3; r++)
        for (int c = 0; c < 4; c++) {
            double s = 0.0;
            for (int k = 0; k < 3; k++) s += (double)K[r*4+k] * (double)e[k*4+c];
            out[r*4+c] = s;
        }
}

__device__ void inv4(const double A[16], double Out[16]) {
    double a[4][8];
    for (int r = 0; r < 4; r++)
        for (int c = 0; c < 4; c++) { a[r][c] = A[r*4+c]; a[r][c+4] = (r == c) ? 1.0 : 0.0; }
    for (int col = 0; col < 4; col++) {
        int piv = col; double best = fabs(a[col][col]);
        for (int r = col+1; r < 4; r++) { double v = fabs(a[r][col]); if (v > best) { best = v; piv = r; } }
        if (piv != col)
            for (int c = 0; c < 8; c++) { double t = a[col][c]; a[col][c] = a[piv][c]; a[piv][c] = t; }
        double d = 1.0 / a[col][col];
        for (int c = 0; c < 8; c++) a[col][c] *= d;
        for (int r = 0; r < 4; r++) {
            if (r == col) continue;
            double f = a[r][col];
            for (int c = 0; c < 8; c++) a[r][c] -= f * a[col][c];
        }
    }
    for (int r = 0; r < 4; r++)
        for (int c = 0; c < 4; c++) Out[r*4+c] = a[r][c+4];
}

__global__ void proj_kernel(const float* __restrict__ pm,
                            const float* __restrict__ dv,
                            const float* __restrict__ pw1, const float* __restrict__ pb1,
                            const float* __restrict__ pw2, const float* __restrict__ pb2,
                            const float* __restrict__ pw3, const float* __restrict__ pb3) {
    int t = threadIdx.x;
    if (blockIdx.x != 0) return;
    if (t < (Vc-1)*Bc) {
        int b = t % Bc;
        int v = t / Bc + 1;
        double ref[16], ri[16], Cm[16];
        combine_mat(pm + ((size_t)b*Vc + 0)*32, ref);
        inv4(ref, ri);
        combine_mat(pm + ((size_t)b*Vc + v)*32, Cm);
        float* P = g_proj[(v-1)*Bc + b];
        for (int r = 0; r < 3; r++) {
            for (int c = 0; c < 4; c++) {
                double s = 0.0;
                for (int k = 0; k < 4; k++) s += Cm[r*4+k] * ri[k*4+c];
                if (c < 3) P[r*3+c] = (float)s;
                else       P[9+r]  = (float)s;
            }
        }
        bool fp = (P[3] == 0.0f && P[4] == 1.0f && P[5] == 0.0f &&
                   P[6] == 0.0f && P[7] == 0.0f && P[8] == 1.0f &&
                   P[10] == 0.0f && P[11] == 0.0f);
        P[12] = fp ? 1.0f : 0.0f;
        for (int d = 0; d < Dc; d++) {
            double dep = (double)dv[((size_t)(b*Dc + d))*HWc];
            g_td[(v-1)*Bc + b][d] = (float)((double)P[9] / dep);
        }
    }
    if (t == 0) {
        float flag = 1.0f;
        for (int j = 0; j < 16; j++) if (pb1[j] != 0.0f) flag = 0.0f;
        for (int k = 0; k < 8;  k++) if (pb2[k] != 0.0f) flag = 0.0f;
        float S = 0.0f;
        for (int k = 0; k < 8; k++) {
            float u = 0.0f;
            for (int j = 0; j < 16; j++) u += pw2[k*16+j] * fmaxf(pw1[j], 0.0f);
            S += pw3[k] * fmaxf(u, 0.0f);
        }
        g_S[0] = S; g_S[1] = pb3[0]; g_S[2] = flag;
        g_dvb[0] = 1.0f;
    }
}

// --------- transpose + dv broadcast check ---------------------------------
__global__ void __launch_bounds__(256) transpose_kernel(const float* __restrict__ f,
                                                        const float* __restrict__ dv) {
    __shared__ float t[32][33];
    int vb  = blockIdx.y;
    int hw0 = blockIdx.x * 32;
    int tid = threadIdx.x;

    size_t gidx = ((size_t)blockIdx.y * gridDim.x + blockIdx.x) * 256 + tid;
    if (gidx < BDHW) {
        size_t bd = gidx / HWc;
        if (dv[gidx] != dv[bd*HWc]) g_dvb[0] = 0.0f;
    }

    #pragma unroll
    for (int i = 0; i < 4; i++) {
        int idx = tid + i*256;
        int ch = idx / 32, hw = idx % 32;
        t[ch][hw] = f[((size_t)vb*Cc + ch)*HWc + hw0 + hw];
    }
    __syncthreads();
    if (vb < Bc) {
        int g = tid / 32, hw = tid % 32;
        float4 o = make_float4(t[4*g+0][hw], t[4*g+1][hw], t[4*g+2][hw], t[4*g+3][hw]);
        ((float4*)g_feat)[((size_t)vb*Gc + g)*HWc + hw0 + hw] = o;
    }
    if (tid < 128) {
        int gp = tid / 32, hw = tid % 32;
        int c0 = gp * 8;
        __half2 a = __floats2half2_rn(t[c0+0][hw], t[c0+1][hw]);
        __half2 b = __floats2half2_rn(t[c0+2][hw], t[c0+3][hw]);
        __half2 c = __floats2half2_rn(t[c0+4][hw], t[c0+5][hw]);
        __half2 dd= __floats2half2_rn(t[c0+6][hw], t[c0+7][hw]);
        uint4 o;
        o.x = *(unsigned int*)&a; o.y = *(unsigned int*)&b;
        o.z = *(unsigned int*)&c; o.w = *(unsigned int*)&dd;
        g_feath[((size_t)vb*4 + gp)*HWc + hw0 + hw] = o;
    }
}

// ------- unified warp + correlation + entropy + vw -------------------------
__global__ void __launch_bounds__(512) warp_sim_kernel(
        const float* __restrict__ dv,
        const float* __restrict__ pw1, const float* __restrict__ pb1,
        const float* __restrict__ pw2, const float* __restrict__ pb2,
        const float* __restrict__ pw3, const float* __restrict__ pb3,
        float* __restrict__ out_vw) {
    __shared__ float sA[256], sB[256];
    int tid = threadIdx.x;
    int lane = tid & 255;
    int dhalf = tid >> 8;
    int pix = blockIdx.x * 256 + lane;
    int b = blockIdx.y;
    int v = blockIdx.z + 1;
    const float* P = g_proj[(v-1)*Bc + b];
    bool fastp = (P[12] != 0.0f);
    int w = pix % Wc, h = pix / Wc;

    float xf = (float)w, yf = (float)h;
    float rx = P[0]*xf + P[1]*yf + P[2];

    const float4* refb = ((const float4*)g_feat) + (size_t)b*Gc*HWc + pix;
    float4 rf[8];
    #pragma unroll
    for (int g = 0; g < 8; g++) rf[g] = refb[(size_t)g*HWc];

    const uint4* fbase = g_feath + (size_t)(v*Bc + b)*4*HWc;
    uint4* gs4 = g_simh4 + ((size_t)((v-1)*Bc + b)*Dc)*HWc + pix;
    const float* dvp = dv + (size_t)b*Dc*HWc + pix;
    const float* tdp = g_td[(v-1)*Bc + b];

    float S = g_S[0], b3f = g_S[1];
    bool slow = (g_S[2] == 0.0f);
    bool dvb  = (g_dvb[0] != 0.0f);
    float redA = 1e30f, redB = -1e30f;
    int rowbase = h * Wc;
    const float L2E = 1.442695041f;

    int d0 = dhalf * (Dc/2);
    int d1 = d0 + (Dc/2);

    #pragma unroll 1
    for (int d = d0; d < d1; d++) {
        float sim[8];
        if (fastp) {
            float x;
            if (dvb) {
                x = rx + tdp[d];
            } else {
                float dep = dvp[(size_t)d*HWc];
                x = __fdividef(rx*dep + P[9], dep);
            }
            float x0f = floorf(x);
            float wx1 = x - x0f;
            float wx0 = 1.0f - wx1;
            float x1f = x0f + 1.0f;
            float vx0 = (x0f >= 0.f && x0f <= (float)(Wc-1)) ? 1.f : 0.f;
            float vx1 = (x1f >= 0.f && x1f <= (float)(Wc-1)) ? 1.f : 0.f;
            int x0 = min(max((int)x0f, 0), Wc-1);
            int x1 = min(max((int)x1f, 0), Wc-1);
            float a0 = wx0*vx0;
            float a1 = wx1*vx1;
            int o0 = rowbase + x0;
            int o1 = rowbase + x1;
            __half2 W0 = __float2half2_rn(a0);
            __half2 W1 = __float2half2_rn(a1);
            #pragma unroll
            for (int gp = 0; gp < 4; gp++) {
                const uint4* fg = fbase + (size_t)gp*HWc;
                uint4 t0 = fg[o0], t1 = fg[o1];
                __half2 b0 = __hmul2(W0, u2h(t0.x)); b0 = __hfma2(W1, u2h(t1.x), b0);
                __half2 b1 = __hmul2(W0, u2h(t0.y)); b1 = __hfma2(W1, u2h(t1.y), b1);
                __half2 b2 = __hmul2(W0, u2h(t0.z)); b2 = __hfma2(W1, u2h(t1.z), b2);
                __half2 b3v= __hmul2(W0, u2h(t0.w)); b3v= __hfma2(W1, u2h(t1.w), b3v);
                float2 f0 = __half22float2(b0);
                float2 f1 = __half22float2(b1);
                float2 f2 = __half22float2(b2);
                float2 f3 = __half22float2(b3v);
                float4 rA = rf[2*gp], rB = rf[2*gp+1];
                sim[2*gp]   = (f0.x*rA.x + f0.y*rA.y + f1.x*rA.z + f1.y*rA.w) * 0.25f;
                sim[2*gp+1] = (f2.x*rB.x + f2.y*rB.y + f3.x*rB.z + f3.y*rB.w) * 0.25f;
            }
        } else {
            float ry = P[3]*xf + P[4]*yf + P[5];
            float rz = P[6]*xf + P[7]*yf + P[8];
            float dep = dvp[(size_t)d*HWc];
            float px = rx*dep + P[9];
            float py = ry*dep + P[10];
            float pz = rz*dep + P[11];
            float x = __fdividef(px, pz);
            float y = __fdividef(py, pz);
            float x0f = floorf(x), y0f = floorf(y);
            float wx1 = x - x0f, wy1 = y - y0f;
            float wx0 = 1.0f - wx1, wy0 = 1.0f - wy1;
            float x1f = x0f + 1.0f, y1f = y0f + 1.0f;
            float vx0 = (x0f >= 0.f && x0f <= (float)(Wc-1)) ? 1.f : 0.f;
            float vx1 = (x1f >= 0.f && x1f <= (float)(Wc-1)) ? 1.f : 0.f;
            float vy0 = (y0f >= 0.f && y0f <= (float)(Hc-1)) ? 1.f : 0.f;
            float vy1 = (y1f >= 0.f && y1f <= (float)(Hc-1)) ? 1.f : 0.f;
            int x0 = min(max((int)x0f, 0), Wc-1);
            int y0 = min(max((int)y0f, 0), Hc-1);
            int x1 = min(max((int)x1f, 0), Wc-1);
            int y1 = min(max((int)y1f, 0), Hc-1);
            float a00 = wx0*wy0*vx0*vy0;
            float a10 = wx1*wy0*vx1*vy0;
            float a01 = wx0*wy1*vx0*vy1;
            float a11 = wx1*wy1*vx1*vy1;
            int o00 = y0*Wc + x0;
            int o10 = y0*Wc + x1;
            int o01 = y1*Wc + x0;
            int o11 = y1*Wc + x1;
            __half2 W00 = __float2half2_rn(a00);
            __half2 W10 = __float2half2_rn(a10);
            __half2 W01 = __float2half2_rn(a01);
            __half2 W11 = __float2half2_rn(a11);
            #pragma unroll
            for (int gp = 0; gp < 4; gp++) {
                const uint4* fg = fbase + (size_t)gp*HWc;
                uint4 t00 = fg[o00], t10 = fg[o10], t01 = fg[o01], t11 = fg[o11];
                __half2 b0 = __hmul2(W00, u2h(t00.x));
                b0 = __hfma2(W10, u2h(t10.x), b0);
                b0 = __hfma2(W01, u2h(t01.x), b0);
                b0 = __hfma2(W11, u2h(t11.x), b0);
                __half2 b1 = __hmul2(W00, u2h(t00.y));
                b1 = __hfma2(W10, u2h(t10.y), b1);
                b1 = __hfma2(W01, u2h(t01.y), b1);
                b1 = __hfma2(W11, u2h(t11.y), b1);
                __half2 b2 = __hmul2(W00, u2h(t00.z));
                b2 = __hfma2(W10, u2h(t10.z), b2);
                b2 = __hfma2(W01, u2h(t01.z), b2);
                b2 = __hfma2(W11, u2h(t11.z), b2);
                __half2 b3v = __hmul2(W00, u2h(t00.w));
                b3v = __hfma2(W10, u2h(t10.w), b3v);
                b3v = __hfma2(W01, u2h(t01.w), b3v);
                b3v = __hfma2(W11, u2h(t11.w), b3v);
                float2 f0 = __half22float2(b0);
                float2 f1 = __half22float2(b1);
                float2 f2 = __half22float2(b2);
                float2 f3 = __half22float2(b3v);
                float4 rA = rf[2*gp], rB = rf[2*gp+1];
                sim[2*gp]   = (f0.x*rA.x + f0.y*rA.y + f1.x*rA.z + f1.y*rA.w) * 0.25f;
                sim[2*gp+1] = (f2.x*rB.x + f2.y*rB.y + f3.x*rB.z + f3.y*rB.w) * 0.25f;
            }
        }

        uint4 pack;
        __half2 h0 = __floats2half2_rn(sim[0], sim[1]);
        __half2 h1 = __floats2half2_rn(sim[2], sim[3]);
        __half2 h2 = __floats2half2_rn(sim[4], sim[5]);
        __half2 h3 = __floats2half2_rn(sim[6], sim[7]);
        pack.x = *(unsigned int*)&h0;
        pack.y = *(unsigned int*)&h1;
        pack.z = *(unsigned int*)&h2;
        pack.w = *(unsigned int*)&h3;
        gs4[(size_t)d*HWc] = pack;

        float m = fmaxf(fmaxf(fmaxf(sim[0], sim[1]), fmaxf(sim[2], sim[3])),
                        fmaxf(fmaxf(sim[4], sim[5]), fmaxf(sim[6], sim[7])));
        float ent;
        if (fastp) {
            float nml = -m * L2E;
            float ssum = 0.0f, wdot = 0.0f;
            #pragma unroll
            for (int g = 0; g < 8; g++) {
                float ex = ex2f(fmaf(sim[g], L2E, nml));
                ssum += ex;
                wdot += ex * sim[g];
            }
            ent = __logf(ssum) + m - __fdividef(wdot, ssum);
        } else {
            float ssum = 0.0f, wdot = 0.0f;
            #pragma unroll
            for (int g = 0; g < 8; g++) {
                float ex = __expf(sim[g] - m);
                ssum += ex;
                wdot += ex * sim[g];
            }
            ent = __logf(ssum) + m - __fdividef(wdot, ssum);
        }

        if (!slow) {
            redA = fminf(redA, ent);
            redB = fmaxf(redB, ent);
        } else {
            float h1a[16];
            for (int j = 0; j < 16; j++) h1a[j] = fmaxf(pw1[j]*ent + pb1[j], 0.0f);
            float o3 = pb3[0];
            for (int k = 0; k < 8; k++) {
                float u = pb2[k];
                for (int j = 0; j < 16; j++) u += pw2[k*16+j]*h1a[j];
                o3 += pw3[k] * fmaxf(u, 0.0f);
            }
            redB = fmaxf(redB, o3);
        }
    }

    if (dhalf == 1) { sA[lane] = redA; sB[lane] = redB; }
    __syncthreads();
    if (dhalf == 0) {
        redA = fminf(redA, sA[lane]);
        redB = fmaxf(redB, sB[lane]);
        float o3m = slow ? redB : (fmaxf(S*redB, S*redA) + b3f);
        out_vw[((size_t)b*(Vc-1) + (v-1))*HWc + pix] = 1.0f / (1.0f + __expf(-o3m));
    }
}

// ------- conv1 (fused combine): 8px x 2out per thread, LDS.128 weights -----
// tile 32w x 8h, halo 36(padded) x 10, D chunk 8
__global__ void __launch_bounds__(128, 5) conv1_kernel(const float* __restrict__ vwbuf,
                                                       const float* __restrict__ w1,
                                                       const float* __restrict__ b1,
                                                       float* __restrict__ out_sim) {
    __shared__ __align__(16) float xs[8*360];                  // [ch][10*36]
    __shared__ __align__(16) unsigned long long wsp[24*80];    // [ikh][og][o2][10]
    __shared__ float vns[4][360];
    __shared__ float bsm[8];
    int tid = threadIdx.x;
    int og = tid >> 5;                 // out channels 2og, 2og+1
    int pid = tid & 31;
    int gx = pid & 3, gy = pid >> 2;   // 8px group (gx*8) in row gy
    int w0 = blockIdx.x * 32, h0 = blockIdx.y * 8;
    int b = blockIdx.z >> 2, s0 = (blockIdx.z & 3) * 8;

    for (int idx = tid; idx < 24*80; idx += 128) {
        int ikh = idx / 80, r = idx % 80;
        int ogx = r / 20, r2 = r % 20;
        int o2 = r2 / 10, k = r2 % 10;
        int i = ikh / 3, kh = ikh % 3;
        int o = ogx*2 + o2;
        float wv = 0.0f;
        if (k < 9) {
            int kd = k / 3, kw = k % 3;
            wv = w1[o*216 + i*27 + kd*9 + kh*3 + kw];
        }
        wsp[idx] = pk2(wv, wv);
    }
    if (tid < 8) bsm[tid] = b1[tid];

    for (int pos = tid; pos < 360; pos += 128) {
        int hh = pos / 36, ww = pos % 36;
        int gh = h0 + hh - 1, gw = w0 + ww - 1;
        float v0 = 0.f, v1 = 0.f, v2 = 0.f, v3 = 0.f;
        if (ww < 34 && (unsigned)gh < (unsigned)Hc && (unsigned)gw < (unsigned)Wc) {
            int pix = gh*Wc + gw;
            v0 = vwbuf[((size_t)b*(Vc-1) + 0)*HWc + pix];
            v1 = vwbuf[((size_t)b*(Vc-1) + 1)*HWc + pix];
            v2 = vwbuf[((size_t)b*(Vc-1) + 2)*HWc + pix];
            v3 = vwbuf[((size_t)b*(Vc-1) + 3)*HWc + pix];
            float iw = 1.0f / (v0 + v1 + v2 + v3 + 1e-6f);
            v0 *= iw; v1 *= iw; v2 *= iw; v3 *= iw;
        }
        vns[0][pos] = v0; vns[1][pos] = v1; vns[2][pos] = v2; vns[3][pos] = v3;
    }

    float* outb = g_c1 + (size_t)b*8*Dc*HWc;

    unsigned long long acc[3][8];     // [phase P,C,N][o2*4 + pair]
    #pragma unroll
    for (int p = 0; p < 3; p++)
        #pragma unroll
        for (int k = 0; k < 8; k++) acc[p][k] = 0ull;

    #pragma unroll 1
    for (int s = s0-1; s <= s0+8; s++) {
        bool have = (s >= 0 && s < Dc);
        __syncthreads();
        if (have) {
            for (int pos = tid; pos < 360; pos += 128) {
                int hh = pos / 36, ww = pos % 36;
                int gh = h0 + hh - 1, gw = w0 + ww - 1;
                float o8[8];
                #pragma unroll
                for (int g = 0; g < 8; g++) o8[g] = 0.0f;
                if (ww < 34 && (unsigned)gh < (unsigned)Hc && (unsigned)gw < (unsigned)Wc) {
                    int pix = gh*Wc + gw;
                    #pragma unroll
                    for (int vv = 0; vv < 4; vv++) {
                        float vn = vns[vv][pos];
                        uint4 raw = g_simh4[((size_t)(vv*Bc + b)*Dc + s)*HWc + pix];
                        float2 s0v = __half22float2(u2h(raw.x));
                        float2 s1v = __half22float2(u2h(raw.y));
                        float2 s2v = __half22float2(u2h(raw.z));
                        float2 s3v = __half22float2(u2h(raw.w));
                        o8[0] += s0v.x*vn; o8[1] += s0v.y*vn;
                        o8[2] += s1v.x*vn; o8[3] += s1v.y*vn;
                        o8[4] += s2v.x*vn; o8[5] += s2v.y*vn;
                        o8[6] += s3v.x*vn; o8[7] += s3v.y*vn;
                    }
                    if (s >= s0 && s < s0 + 8 &&
                        hh >= 1 && hh <= 8 && ww >= 1 && ww <= 32) {
                        #pragma unroll
                        for (int g = 0; g < 8; g++)
                            out_sim[((size_t)(b*8 + g)*Dc + s)*HWc + pix] = o8[g];
                    }
                }
                #pragma unroll
                for (int g = 0; g < 8; g++)
                    xs[g*360 + pos] = o8[g];
            }
        }
        __syncthreads();
        if (have) {
            #pragma unroll 1
            for (int i = 0; i < 8; i++) {
                #pragma unroll
                for (int kh = 0; kh < 3; kh++) {
                    const float2* row = (const float2*)&xs[(i*10 + gy + kh)*36 + gx*8];
                    float2 q0 = row[0], q1 = row[1], q2 = row[2], q3 = row[3], q4 = row[4];
                    unsigned long long P0 = pk2(q0.x, q0.y);
                    unsigned long long P1 = pk2(q1.x, q1.y);
                    unsigned long long P2 = pk2(q2.x, q2.y);
                    unsigned long long P3 = pk2(q3.x, q3.y);
                    unsigned long long P4 = pk2(q4.x, q4.y);
                    unsigned long long M0 = pk2(q0.y, q1.x);
                    unsigned long long M1 = pk2(q1.y, q2.x);
                    unsigned long long M2 = pk2(q2.y, q3.x);
                    unsigned long long M3 = pk2(q3.y, q4.x);
                    const unsigned long long* wb = &wsp[(i*3 + kh)*80 + og*20];
                    #pragma unroll
                    for (int o2 = 0; o2 < 2; o2++) {
                        const ulonglong2* wp2 = (const ulonglong2*)(wb + o2*10);
                        ulonglong2 a0 = wp2[0];   // w0 w1
                        ulonglong2 a1 = wp2[1];   // w2 w3
                        ulonglong2 a2 = wp2[2];   // w4 w5
                        ulonglong2 a3 = wp2[3];   // w6 w7
                        ulonglong2 a4 = wp2[4];   // w8 pad
                        unsigned long long* apN = &acc[2][o2*4];  // kd=0
                        fma2(apN[0], a0.x, P0); fma2(apN[1], a0.x, P1);
                        fma2(apN[2], a0.x, P2); fma2(apN[3], a0.x, P3);
                        fma2(apN[0], a0.y, M0); fma2(apN[1], a0.y, M1);
                        fma2(apN[2], a0.y, M2); fma2(apN[3], a0.y, M3);
                        fma2(apN[0], a1.x, P1); fma2(apN[1], a1.x, P2);
                        fma2(apN[2], a1.x, P3); fma2(apN[3], a1.x, P4);
                        unsigned long long* apC = &acc[1][o2*4];  // kd=1
                        fma2(apC[0], a1.y, P0); fma2(apC[1], a1.y, P1);
                        fma2(apC[2], a1.y, P2); fma2(apC[3], a1.y, P3);
                        fma2(apC[0], a2.x, M0); fma2(apC[1], a2.x, M1);
                        fma2(apC[2], a2.x, M2); fma2(apC[3], a2.x, M3);
                        fma2(apC[0], a2.y, P1); fma2(apC[1], a2.y, P2);
                        fma2(apC[2], a2.y, P3); fma2(apC[3], a2.y, P4);
                        unsigned long long* apP = &acc[0][o2*4];  // kd=2
                        fma2(apP[0], a3.x, P0); fma2(apP[1], a3.x, P1);
                        fma2(apP[2], a3.x, P2); fma2(apP[3], a3.x, P3);
                        fma2(apP[0], a3.y, M0); fma2(apP[1], a3.y, M1);
                        fma2(apP[2], a3.y, M2); fma2(apP[3], a3.y, M3);
                        fma2(apP[0], a4.x, P1); fma2(apP[1], a4.x, P2);
                        fma2(apP[2], a4.x, P3); fma2(apP[3], a4.x, P4);
                    }
                }
            }
        }
        int so = s - 1;
        if (so >= s0 && so < s0 + 8) {
            size_t pb = (size_t)so*HWc + (h0+gy)*Wc + (w0 + gx*8);
            #pragma unroll
            for (int o2 = 0; o2 < 2; o2++) {
                int o = 2*og + o2;
                float bb = bsm[o];
                float2 r0 = upk2(acc[0][o2*4+0]);
                float2 r1 = upk2(acc[0][o2*4+1]);
                float2 r2 = upk2(acc[0][o2*4+2]);
                float2 r3 = upk2(acc[0][o2*4+3]);
                float4 ovA = make_float4(fmaxf(r0.x+bb,0.f), fmaxf(r0.y+bb,0.f),
                                         fmaxf(r1.x+bb,0.f), fmaxf(r1.y+bb,0.f));
                float4 ovB = make_float4(fmaxf(r2.x+bb,0.f), fmaxf(r2.y+bb,0.f),
                                         fmaxf(r3.x+bb,0.f), fmaxf(r3.y+bb,0.f));
                *(float4*)&outb[(size_t)o*Dc*HWc + pb]     = ovA;
                *(float4*)&outb[(size_t)o*Dc*HWc + pb + 4] = ovB;
            }
        }
        #pragma unroll
        for (int k = 0; k < 8; k++) {
            acc[0][k] = acc[1][k];
            acc[1][k] = acc[2][k];
            acc[2][k] = 0ull;
        }
    }
}

// ---------------- conv3d 8->1, 3x3x3, pad 1 (unchanged) --------------------
#define TW 32
#define TH 16
#define DCH 8
__global__ void __launch_bounds__(128) conv2_kernel(const float* __restrict__ w2,
                                                    const float* __restrict__ b2,
                                                    float* __restrict__ out_pvp) {
    __shared__ float  xs[8*18*34];
    __shared__ float4 wsm[8*3*3];
    __shared__ float  bias;
    int tid = threadIdx.x;
    int tx = tid & 7, ty = tid >> 3;
    int w0 = blockIdx.x * TW, h0 = blockIdx.y * TH;
    int b = blockIdx.z >> 2, s0 = (blockIdx.z & 3) * DCH;
    int lx = tx * 4;

    for (int idx = tid; idx < 8*3*3; idx += 128) {
        int i = idx / 9, r = idx % 9;
        int kh = r / 3, kd = r % 3;
        const float* wp = w2 + i*27 + kd*9 + kh*3;
        wsm[idx] = make_float4(wp[0], wp[1], wp[2], 0.f);
    }
    if (tid == 0) bias = b2[0];

    const float* base = g_c1 + (size_t)b*8*Dc*HWc;

    unsigned long long aP[2], aC[2], aN[2];
    aP[0]=aP[1]=aC[0]=aC[1]=aN[0]=aN[1]=0ull;

    #pragma unroll 1
    for (int s = s0-1; s <= s0+DCH; s++) {
        bool have = (s >= 0 && s < Dc);
        __syncthreads();
        if (have) {
            for (int idx = tid; idx < 8*18*34; idx += 128) {
                int i = idx / (18*34), r = idx % (18*34);
                int hh = r / 34, ww = r % 34;
                int gh = h0 + hh - 1, gw = w0 + ww - 1;
                float val = 0.0f;
                if ((unsigned)gh < (unsigned)Hc && (unsigned)gw < (unsigned)Wc)
                    val = base[((size_t)i*Dc + s)*HWc + gh*Wc + gw];
                xs[idx] = val;
            }
        }
        __syncthreads();
        if (have) {
            #pragma unroll 1
            for (int i = 0; i < 8; i++) {
                #pragma unroll
                for (int kh = 0; kh < 3; kh++) {
                    const float* row = &xs[(i*18 + ty + kh)*34 + lx];
                    float2 q0 = *(const float2*)(row);
                    float2 q1 = *(const float2*)(row+2);
                    float2 q2 = *(const float2*)(row+4);
                    unsigned long long A0 = pk2(q0.x, q0.y);
                    unsigned long long B0 = pk2(q1.x, q1.y);
                    unsigned long long A1 = pk2(q0.y, q1.x);
                    unsigned long long B1 = pk2(q1.y, q2.x);
                    unsigned long long C0 = pk2(q2.x, q2.y);
                    float4 wn = wsm[(i*3+kh)*3+0];
                    float4 wc = wsm[(i*3+kh)*3+1];
                    float4 wv = wsm[(i*3+kh)*3+2];
                    unsigned long long t;
                    t = pk2(wn.x,wn.x); fma2(aN[0],t,A0); fma2(aN[1],t,B0);
                    t = pk2(wn.y,wn.y); fma2(aN[0],t,A1); fma2(aN[1],t,B1);
                    t = pk2(wn.z,wn.z); fma2(aN[0],t,B0); fma2(aN[1],t,C0);
                    t = pk2(wc.x,wc.x); fma2(aC[0],t,A0); fma2(aC[1],t,B0);
                    t = pk2(wc.y,wc.y); fma2(aC[0],t,A1); fma2(aC[1],t,B1);
                    t = pk2(wc.z,wc.z); fma2(aC[0],t,B0); fma2(aC[1],t,C0);
                    t = pk2(wv.x,wv.x); fma2(aP[0],t,A0); fma2(aP[1],t,B0);
                    t = pk2(wv.y,wv.y); fma2(aP[0],t,A1); fma2(aP[1],t,B1);
                    t = pk2(wv.z,wv.z); fma2(aP[0],t,B0); fma2(aP[1],t,C0);
                }
            }
        }
        int so = s - 1;
        if (so >= s0 && so < s0 + DCH) {
            float2 pA = upk2(aP[0]), pB = upk2(aP[1]);
            float4 ov = make_float4(pA.x+bias, pA.y+bias, pB.x+bias, pB.y+bias);
            *(float4*)&out_pvp[((size_t)b*Dc + so)*HWc + (h0+ty)*Wc + (w0+lx)] = ov;
        }
        aP[0]=aC[0]; aP[1]=aC[1]; aC[0]=aN[0]; aC[1]=aN[1]; aN[0]=0ull; aN[1]=0ull;
    }
}

// ---------------- depth softmax + expectation + confidence -----------------
__global__ void final_kernel(const float* __restrict__ pvp,
                             const float* __restrict__ dv,
                             float* __restrict__ depth_out,
                             float* __restrict__ conf_out) {
    int p = blockIdx.x * blockDim.x + threadIdx.x;
    if (p >= BHW) return;
    int b = p / HWc, pix = p % HWc;
    const float* vp  = pvp + (size_t)b*Dc*HWc + pix;
    const float* dvp = dv  + (size_t)b*Dc*HWc + pix;

    float x[Dc];
    float m = -1e30f;
    #pragma unroll
    for (int d = 0; d < Dc; d++) { x[d] = vp[(size_t)d*HWc]; m = fmaxf(m, x[d]); }
    float s = 0.0f;
    #pragma unroll
    for (int d = 0; d < Dc; d++) { x[d] = __expf(x[d] - m); s += x[d]; }
    float inv_s = 1.0f / s;
    float depth = 0.0f, dif = 0.0f;
    #pragma unroll
    for (int d = 0; d < Dc; d++) {
        float pd = x[d] * inv_s;
        x[d] = pd;
        depth += pd * dvp[(size_t)d*HWc];
        dif += pd * (float)d;
    }
    int di = min(max((int)dif, 0), Dc-1);
    float c4 = 0.0f;
    #pragma unroll
    for (int d = 0; d < Dc; d++) {
        bool in = (d >= di - 1) && (d <= di + 2);
        c4 += in ? x[d] : 0.0f;
    }
    depth_out[p] = depth;
    conf_out[p] = c4;
}

// ---------------- launch ----------------------------------------------------
extern "C" void kernel_launch(void* const* d_in, const int* in_sizes, int n_in,
                              void* d_out, int out_size) {
    const float* features = (const float*)d_in[0];
    const float* pm       = (const float*)d_in[1];
    const float* dv       = (const float*)d_in[2];
    const float* rw1      = (const float*)d_in[3];
    const float* rb1      = (const float*)d_in[4];
    const float* rw2      = (const float*)d_in[5];
    const float* rb2      = (const float*)d_in[6];
    const float* pw1      = (const float*)d_in[7];
    const float* pb1      = (const float*)d_in[8];
    const float* pw2      = (const float*)d_in[9];
    const float* pb2      = (const float*)d_in[10];
    const float* pw3      = (const float*)d_in[11];
    const float* pb3      = (const float*)d_in[12];

    float* out       = (float*)d_out;
    float* out_depth = out;
    float* out_conf  = out + BHW;
    float* out_vw    = out + 2*BHW;
    float* out_pvp   = out + 2*BHW + (Vc-1)*BHW;
    float* out_sim   = out_pvp + BDHW;

    proj_kernel<<<1, 32>>>(pm, dv, pw1, pb1, pw2, pb2, pw3, pb3);       // 1

    {
        dim3 grd(HWc/32, Vc*Bc);
        transpose_kernel<<<grd, 256>>>(features, dv);                   // 2
    }
    {
        dim3 grd(HWc/256, Bc, Vc-1);
        warp_sim_kernel<<<grd, 512>>>(dv, pw1, pb1, pw2, pb2, pw3, pb3, out_vw);  // 3
    }
    {
        dim3 grd1(Wc/32, Hc/8, Bc*4);
        conv1_kernel<<<grd1, 128>>>(out_vw, rw1, rb1, out_sim);         // 4 <- profiled
        dim3 grd2(Wc/TW, Hc/TH, Bc*(Dc/DCH));
        conv2_kernel<<<grd2, 128>>>(rw2, rb2, out_pvp);                 // 5
    }

    final_kernel<<<(BHW + 255)/256, 256>>>(out_pvp, dv, out_depth, out_conf);  // 6
}

// round 17
// speedup vs baseline: 1.7312x; 1.7312x over previous
#include <cuda_runtime.h>
#include <cuda_fp16.h>
#include <math.h>

#define Bc 2
#define Vc 5
#define Cc 32
#define Hc 128
#define Wc 160
#define Dc 32
#define Gc 8
#define HWc (Hc*Wc)            // 20480
#define BHW (Bc*HWc)           // 40960
#define BDHW (Bc*Dc*HWc)       // 1310720

// ---------------- scratch (device globals) ----------------
__device__ uint4   g_simh4[(size_t)(Vc-1)*Bc*Dc*HWc];    // sim: 8 half per voxel
__device__ float   g_feat[(size_t)Bc*Cc*HWc];            // view-0 fp32 (B,G,HW,4)
__device__ uint4   g_feath[(size_t)Vc*Bc*4*HWc];         // all views half (VB,4pl,HW)
__device__ float   g_c1[(size_t)Bc*8*Dc*HWc];            // conv1 output
__device__ float   g_proj[(Vc-1)*Bc][16];                // R(9)+t(3)+fastflag
__device__ float   g_td[(Vc-1)*Bc][Dc];                  // t_d = P9/dep_d
__device__ float   g_S[4];                               // S, b3, flag
__device__ float   g_dvb[1];                             // dv-broadcast flag

// ---------------- helpers ----------------
__device__ __forceinline__ unsigned long long pk2(float lo, float hi) {
    unsigned long long r;
    asm("mov.b64 %0, {%1,%2};" : "=l"(r) : "f"(lo), "f"(hi));
    return r;
}
__device__ __forceinline__ void fma2(unsigned long long& d,
                                     unsigned long long a, unsigned long long b) {
    asm("fma.rn.f32x2 %0, %1, %2, %0;" : "+l"(d) : "l"(a), "l"(b));
}
__device__ __forceinline__ float2 upk2(unsigned long long v) {
    float2 r;
    asm("mov.b64 {%0,%1}, %2;" : "=f"(r.x), "=f"(r.y) : "l"(v));
    return r;
}
__device__ __forceinline__ __half2 u2h(unsigned int u) { return *(__half2*)&u; }
__device__ __forceinline__ float ex2f(float x) {
    float r;
    asm("ex2.approx.f32 %0, %1;" : "=f"(r) : "f"(x));
    return r;
}

// ---------------- projection + MLP-fold setup ----------------
__device__ void combine_mat(const float* pm, double out[16]) {
    const float* e = pm;
    const float* K = pm + 16;
    for (int r = 0; r < 4; r++)
        for (int c = 0; c < 4; c++)
            out[r*4+c] = (double)e[r*4+c];
    for (int r = 0; r < 3; r++)
        for (int c = 0; c < 4; c++) {
            double s = 0.0;
            for (int k = 0; k < 3; k++) s += (double)K[r*4+k] * (double)e[k*4+c];
            out[r*4+c] = s;
        }
}

__device__ void inv4(const double A[16], double Out[16]) {
    double a[4][8];
    for (int r = 0; r < 4; r++)
        for (int c = 0; c < 4; c++) { a[r][c] = A[r*4+c]; a[r][c+4] = (r == c) ? 1.0 : 0.0; }
    for (int col = 0; col < 4; col++) {
        int piv = col; double best = fabs(a[col][col]);
        for (int r = col+1; r < 4; r++) { double v = fabs(a[r][col]); if (v > best) { best = v; piv = r; } }
        if (piv != col)
            for (int c = 0; c < 8; c++) { double t = a[col][c]; a[col][c] = a[piv][c]; a[piv][c] = t; }
        double d = 1.0 / a[col][col];
        for (int c = 0; c < 8; c++) a[col][c] *= d;
        for (int r = 0; r < 4; r++) {
            if (r == col) continue;
            double f = a[r][col];
            for (int c = 0; c < 8; c++) a[r][c] -= f * a[col][c];
        }
    }
    for (int r = 0; r < 4; r++)
        for (int c = 0; c < 4; c++) Out[r*4+c] = a[r][c+4];
}

__global__ void proj_kernel(const float* __restrict__ pm,
                            const float* __restrict__ dv,
                            const float* __restrict__ pw1, const float* __restrict__ pb1,
                            const float* __restrict__ pw2, const float* __restrict__ pb2,
                            const float* __restrict__ pw3, const float* __restrict__ pb3) {
    int t = threadIdx.x;
    if (blockIdx.x != 0) return;
    if (t < (Vc-1)*Bc) {
        int b = t % Bc;
        int v = t / Bc + 1;
        double ref[16], ri[16], Cm[16];
        combine_mat(pm + ((size_t)b*Vc + 0)*32, ref);
        inv4(ref, ri);
        combine_mat(pm + ((size_t)b*Vc + v)*32, Cm);
        float* P = g_proj[(v-1)*Bc + b];
        for (int r = 0; r < 3; r++) {
            for (int c = 0; c < 4; c++) {
                double s = 0.0;
                for (int k = 0; k < 4; k++) s += Cm[r*4+k] * ri[k*4+c];
                if (c < 3) P[r*3+c] = (float)s;
                else       P[9+r]  = (float)s;
            }
        }
        bool fp = (P[3] == 0.0f && P[4] == 1.0f && P[5] == 0.0f &&
                   P[6] == 0.0f && P[7] == 0.0f && P[8] == 1.0f &&
                   P[10] == 0.0f && P[11] == 0.0f);
        P[12] = fp ? 1.0f : 0.0f;
        for (int d = 0; d < Dc; d++) {
            double dep = (double)dv[((size_t)(b*Dc + d))*HWc];
            g_td[(v-1)*Bc + b][d] = (float)((double)P[9] / dep);
        }
    }
    if (t == 0) {
        float flag = 1.0f;
        for (int j = 0; j < 16; j++) if (pb1[j] != 0.0f) flag = 0.0f;
        for (int k = 0; k < 8;  k++) if (pb2[k] != 0.0f) flag = 0.0f;
        float S = 0.0f;
        for (int k = 0; k < 8; k++) {
            float u = 0.0f;
            for (int j = 0; j < 16; j++) u += pw2[k*16+j] * fmaxf(pw1[j], 0.0f);
            S += pw3[k] * fmaxf(u, 0.0f);
        }
        g_S[0] = S; g_S[1] = pb3[0]; g_S[2] = flag;
        g_dvb[0] = 1.0f;
    }
}

// --------- transpose + dv broadcast check ---------------------------------
__global__ void __launch_bounds__(256) transpose_kernel(const float* __restrict__ f,
                                                        const float* __restrict__ dv) {
    __shared__ float t[32][33];
    int vb  = blockIdx.y;
    int hw0 = blockIdx.x * 32;
    int tid = threadIdx.x;

    size_t gidx = ((size_t)blockIdx.y * gridDim.x + blockIdx.x) * 256 + tid;
    if (gidx < BDHW) {
        size_t bd = gidx / HWc;
        if (dv[gidx] != dv[bd*HWc]) g_dvb[0] = 0.0f;
    }

    #pragma unroll
    for (int i = 0; i < 4; i++) {
        int idx = tid + i*256;
        int ch = idx / 32, hw = idx % 32;
        t[ch][hw] = f[((size_t)vb*Cc + ch)*HWc + hw0 + hw];
    }
    __syncthreads();
    if (vb < Bc) {
        int g = tid / 32, hw = tid % 32;
        float4 o = make_float4(t[4*g+0][hw], t[4*g+1][hw], t[4*g+2][hw], t[4*g+3][hw]);
        ((float4*)g_feat)[((size_t)vb*Gc + g)*HWc + hw0 + hw] = o;
    }
    if (tid < 128) {
        int gp = tid / 32, hw = tid % 32;
        int c0 = gp * 8;
        __half2 a = __floats2half2_rn(t[c0+0][hw], t[c0+1][hw]);
        __half2 b = __floats2half2_rn(t[c0+2][hw], t[c0+3][hw]);
        __half2 c = __floats2half2_rn(t[c0+4][hw], t[c0+5][hw]);
        __half2 dd= __floats2half2_rn(t[c0+6][hw], t[c0+7][hw]);
        uint4 o;
        o.x = *(unsigned int*)&a; o.y = *(unsigned int*)&b;
        o.z = *(unsigned int*)&c; o.w = *(unsigned int*)&dd;
        g_feath[((size_t)vb*4 + gp)*HWc + hw0 + hw] = o;
    }
}

// ------- unified warp + correlation + entropy + vw -------------------------
__global__ void __launch_bounds__(512) warp_sim_kernel(
        const float* __restrict__ dv,
        const float* __restrict__ pw1, const float* __restrict__ pb1,
        const float* __restrict__ pw2, const float* __restrict__ pb2,
        const float* __restrict__ pw3, const float* __restrict__ pb3,
        float* __restrict__ out_vw) {
    __shared__ float sA[256], sB[256];
    int tid = threadIdx.x;
    int lane = tid & 255;
    int dhalf = tid >> 8;
    int pix = blockIdx.x * 256 + lane;
    int b = blockIdx.y;
    int v = blockIdx.z + 1;
    const float* P = g_proj[(v-1)*Bc + b];
    bool fastp = (P[12] != 0.0f);
    int w = pix % Wc, h = pix / Wc;

    float xf = (float)w, yf = (float)h;
    float rx = P[0]*xf + P[1]*yf + P[2];

    const float4* refb = ((const float4*)g_feat) + (size_t)b*Gc*HWc + pix;
    float4 rf[8];
    #pragma unroll
    for (int g = 0; g < 8; g++) rf[g] = refb[(size_t)g*HWc];

    const uint4* fbase = g_feath + (size_t)(v*Bc + b)*4*HWc;
    uint4* gs4 = g_simh4 + ((size_t)((v-1)*Bc + b)*Dc)*HWc + pix;
    const float* dvp = dv + (size_t)b*Dc*HWc + pix;
    const float* tdp = g_td[(v-1)*Bc + b];

    float S = g_S[0], b3f = g_S[1];
    bool slow = (g_S[2] == 0.0f);
    bool dvb  = (g_dvb[0] != 0.0f);
    float redA = 1e30f, redB = -1e30f;
    int rowbase = h * Wc;
    const float L2E = 1.442695041f;

    int d0 = dhalf * (Dc/2);
    int d1 = d0 + (Dc/2);

    #pragma unroll 1
    for (int d = d0; d < d1; d++) {
        float sim[8];
        if (fastp) {
            float x;
            if (dvb) {
                x = rx + tdp[d];
            } else {
                float dep = dvp[(size_t)d*HWc];
                x = __fdividef(rx*dep + P[9], dep);
            }
            float x0f = floorf(x);
            float wx1 = x - x0f;
            float wx0 = 1.0f - wx1;
            float x1f = x0f + 1.0f;
            float vx0 = (x0f >= 0.f && x0f <= (float)(Wc-1)) ? 1.f : 0.f;
            float vx1 = (x1f >= 0.f && x1f <= (float)(Wc-1)) ? 1.f : 0.f;
            int x0 = min(max((int)x0f, 0), Wc-1);
            int x1 = min(max((int)x1f, 0), Wc-1);
            float a0 = wx0*vx0;
            float a1 = wx1*vx1;
            int o0 = rowbase + x0;
            int o1 = rowbase + x1;
            __half2 W0 = __float2half2_rn(a0);
            __half2 W1 = __float2half2_rn(a1);
            #pragma unroll
            for (int gp = 0; gp < 4; gp++) {
                const uint4* fg = fbase + (size_t)gp*HWc;
                uint4 t0 = fg[o0], t1 = fg[o1];
                __half2 b0 = __hmul2(W0, u2h(t0.x)); b0 = __hfma2(W1, u2h(t1.x), b0);
                __half2 b1 = __hmul2(W0, u2h(t0.y)); b1 = __hfma2(W1, u2h(t1.y), b1);
                __half2 b2 = __hmul2(W0, u2h(t0.z)); b2 = __hfma2(W1, u2h(t1.z), b2);
                __half2 b3v= __hmul2(W0, u2h(t0.w)); b3v= __hfma2(W1, u2h(t1.w), b3v);
                float2 f0 = __half22float2(b0);
                float2 f1 = __half22float2(b1);
                float2 f2 = __half22float2(b2);
                float2 f3 = __half22float2(b3v);
                float4 rA = rf[2*gp], rB = rf[2*gp+1];
                sim[2*gp]   = (f0.x*rA.x + f0.y*rA.y + f1.x*rA.z + f1.y*rA.w) * 0.25f;
                sim[2*gp+1] = (f2.x*rB.x + f2.y*rB.y + f3.x*rB.z + f3.y*rB.w) * 0.25f;
            }
        } else {
            float ry = P[3]*xf + P[4]*yf + P[5];
            float rz = P[6]*xf + P[7]*yf + P[8];
            float dep = dvp[(size_t)d*HWc];
            float px = rx*dep + P[9];
            float py = ry*dep + P[10];
            float pz = rz*dep + P[11];
            float x = __fdividef(px, pz);
            float y = __fdividef(py, pz);
            float x0f = floorf(x), y0f = floorf(y);
            float wx1 = x - x0f, wy1 = y - y0f;
            float wx0 = 1.0f - wx1, wy0 = 1.0f - wy1;
            float x1f = x0f + 1.0f, y1f = y0f + 1.0f;
            float vx0 = (x0f >= 0.f && x0f <= (float)(Wc-1)) ? 1.f : 0.f;
            float vx1 = (x1f >= 0.f && x1f <= (float)(Wc-1)) ? 1.f : 0.f;
            float vy0 = (y0f >= 0.f && y0f <= (float)(Hc-1)) ? 1.f : 0.f;
            float vy1 = (y1f >= 0.f && y1f <= (float)(Hc-1)) ? 1.f : 0.f;
            int x0 = min(max((int)x0f, 0), Wc-1);
            int y0 = min(max((int)y0f, 0), Hc-1);
            int x1 = min(max((int)x1f, 0), Wc-1);
            int y1 = min(max((int)y1f, 0), Hc-1);
            float a00 = wx0*wy0*vx0*vy0;
            float a10 = wx1*wy0*vx1*vy0;
            float a01 = wx0*wy1*vx0*vy1;
            float a11 = wx1*wy1*vx1*vy1;
            int o00 = y0*Wc + x0;
            int o10 = y0*Wc + x1;
            int o01 = y1*Wc + x0;
            int o11 = y1*Wc + x1;
            __half2 W00 = __float2half2_rn(a00);
            __half2 W10 = __float2half2_rn(a10);
            __half2 W01 = __float2half2_rn(a01);
            __half2 W11 = __float2half2_rn(a11);
            #pragma unroll
            for (int gp = 0; gp < 4; gp++) {
                const uint4* fg = fbase + (size_t)gp*HWc;
                uint4 t00 = fg[o00], t10 = fg[o10], t01 = fg[o01], t11 = fg[o11];
                __half2 b0 = __hmul2(W00, u2h(t00.x));
                b0 = __hfma2(W10, u2h(t10.x), b0);
                b0 = __hfma2(W01, u2h(t01.x), b0);
                b0 = __hfma2(W11, u2h(t11.x), b0);
                __half2 b1 = __hmul2(W00, u2h(t00.y));
                b1 = __hfma2(W10, u2h(t10.y), b1);
                b1 = __hfma2(W01, u2h(t01.y), b1);
                b1 = __hfma2(W11, u2h(t11.y), b1);
                __half2 b2 = __hmul2(W00, u2h(t00.z));
                b2 = __hfma2(W10, u2h(t10.z), b2);
                b2 = __hfma2(W01, u2h(t01.z), b2);
                b2 = __hfma2(W11, u2h(t11.z), b2);
                __half2 b3v = __hmul2(W00, u2h(t00.w));
                b3v = __hfma2(W10, u2h(t10.w), b3v);
                b3v = __hfma2(W01, u2h(t01.w), b3v);
                b3v = __hfma2(W11, u2h(t11.w), b3v);
                float2 f0 = __half22float2(b0);
                float2 f1 = __half22float2(b1);
                float2 f2 = __half22float2(b2);
                float2 f3 = __half22float2(b3v);
                float4 rA = rf[2*gp], rB = rf[2*gp+1];
                sim[2*gp]   = (f0.x*rA.x + f0.y*rA.y + f1.x*rA.z + f1.y*rA.w) * 0.25f;
                sim[2*gp+1] = (f2.x*rB.x + f2.y*rB.y + f3.x*rB.z + f3.y*rB.w) * 0.25f;
            }
        }

        uint4 pack;
        __half2 h0 = __floats2half2_rn(sim[0], sim[1]);
        __half2 h1 = __floats2half2_rn(sim[2], sim[3]);
        __half2 h2 = __floats2half2_rn(sim[4], sim[5]);
        __half2 h3 = __floats2half2_rn(sim[6], sim[7]);
        pack.x = *(unsigned int*)&h0;
        pack.y = *(unsigned int*)&h1;
        pack.z = *(unsigned int*)&h2;
        pack.w = *(unsigned int*)&h3;
        gs4[(size_t)d*HWc] = pack;

        float m = fmaxf(fmaxf(fmaxf(sim[0], sim[1]), fmaxf(sim[2], sim[3])),
                        fmaxf(fmaxf(sim[4], sim[5]), fmaxf(sim[6], sim[7])));
        float ent;
        if (fastp) {
            float nml = -m * L2E;
            float ssum = 0.0f, wdot = 0.0f;
            #pragma unroll
            for (int g = 0; g < 8; g++) {
                float ex = ex2f(fmaf(sim[g], L2E, nml));
                ssum += ex;
                wdot += ex * sim[g];
            }
            ent = __logf(ssum) + m - __fdividef(wdot, ssum);
        } else {
            float ssum = 0.0f, wdot = 0.0f;
            #pragma unroll
            for (int g = 0; g < 8; g++) {
                float ex = __expf(sim[g] - m);
                ssum += ex;
                wdot += ex * sim[g];
            }
            ent = __logf(ssum) + m - __fdividef(wdot, ssum);
        }

        if (!slow) {
            redA = fminf(redA, ent);
            redB = fmaxf(redB, ent);
        } else {
            float h1a[16];
            for (int j = 0; j < 16; j++) h1a[j] = fmaxf(pw1[j]*ent + pb1[j], 0.0f);
            float o3 = pb3[0];
            for (int k = 0; k < 8; k++) {
                float u = pb2[k];
                for (int j = 0; j < 16; j++) u += pw2[k*16+j]*h1a[j];
                o3 += pw3[k] * fmaxf(u, 0.0f);
            }
            redB = fmaxf(redB, o3);
        }
    }

    if (dhalf == 1) { sA[lane] = redA; sB[lane] = redB; }
    __syncthreads();
    if (dhalf == 0) {
        redA = fminf(redA, sA[lane]);
        redB = fmaxf(redB, sB[lane]);
        float o3m = slow ? redB : (fmaxf(S*redB, S*redA) + b3f);
        out_vw[((size_t)b*(Vc-1) + (v-1))*HWc + pix] = 1.0f / (1.0f + __expf(-o3m));
    }
}

// ------- conv1 (fused combine): 8px x 2out per thread (R15 body, 5 blk/SM) -
// tile 32w x 8h, halo 36(padded) x 10, D chunk 8
__global__ void __launch_bounds__(128, 5) conv1_kernel(const float* __restrict__ vwbuf,
                                                       const float* __restrict__ w1,
                                                       const float* __restrict__ b1,
                                                       float* __restrict__ out_sim) {
    __shared__ __align__(16) float xs[8*360];            // [ch][10*36]
    __shared__ unsigned long long wsp[1728];             // [(i*3+kh)*72 + o*9 + kd*3 + kw]
    __shared__ float vns[4][360];
    __shared__ float bsm[8];
    int tid = threadIdx.x;
    int og = tid >> 5;                 // out channels 2og, 2og+1
    int pid = tid & 31;
    int gx = pid & 3, gy = pid >> 2;   // 8px group (gx*8) in row gy
    int w0 = blockIdx.x * 32, h0 = blockIdx.y * 8;
    int b = blockIdx.z >> 2, s0 = (blockIdx.z & 3) * 8;

    for (int idx = tid; idx < 1728; idx += 128) {
        int ikh = idx / 72, r = idx % 72;
        int o = r / 9, r2 = r % 9;
        int kd = r2 / 3, kw = r2 % 3;
        int i = ikh / 3, kh = ikh % 3;
        float wv = w1[o*216 + i*27 + kd*9 + kh*3 + kw];
        wsp[idx] = pk2(wv, wv);
    }
    if (tid < 8) bsm[tid] = b1[tid];

    for (int pos = tid; pos < 360; pos += 128) {
        int hh = pos / 36, ww = pos % 36;
        int gh = h0 + hh - 1, gw = w0 + ww - 1;
        float v0 = 0.f, v1 = 0.f, v2 = 0.f, v3 = 0.f;
        if (ww < 34 && (unsigned)gh < (unsigned)Hc && (unsigned)gw < (unsigned)Wc) {
            int pix = gh*Wc + gw;
            v0 = vwbuf[((size_t)b*(Vc-1) + 0)*HWc + pix];
            v1 = vwbuf[((size_t)b*(Vc-1) + 1)*HWc + pix];
            v2 = vwbuf[((size_t)b*(Vc-1) + 2)*HWc + pix];
            v3 = vwbuf[((size_t)b*(Vc-1) + 3)*HWc + pix];
            float iw = 1.0f / (v0 + v1 + v2 + v3 + 1e-6f);
            v0 *= iw; v1 *= iw; v2 *= iw; v3 *= iw;
        }
        vns[0][pos] = v0; vns[1][pos] = v1; vns[2][pos] = v2; vns[3][pos] = v3;
    }

    float* outb = g_c1 + (size_t)b*8*Dc*HWc;

    unsigned long long acc[3][8];     // [phase P,C,N][o2*4 + pair]
    #pragma unroll
    for (int p = 0; p < 3; p++)
        #pragma unroll
        for (int k = 0; k < 8; k++) acc[p][k] = 0ull;

    #pragma unroll 1
    for (int s = s0-1; s <= s0+8; s++) {
        bool have = (s >= 0 && s < Dc);
        __syncthreads();
        if (have) {
            for (int pos = tid; pos < 360; pos += 128) {
                int hh = pos / 36, ww = pos % 36;
                int gh = h0 + hh - 1, gw = w0 + ww - 1;
                float o8[8];
                #pragma unroll
                for (int g = 0; g < 8; g++) o8[g] = 0.0f;
                if (ww < 34 && (unsigned)gh < (unsigned)Hc && (unsigned)gw < (unsigned)Wc) {
                    int pix = gh*Wc + gw;
                    #pragma unroll
                    for (int vv = 0; vv < 4; vv++) {
                        float vn = vns[vv][pos];
                        uint4 raw = g_simh4[((size_t)(vv*Bc + b)*Dc + s)*HWc + pix];
                        float2 s0v = __half22float2(u2h(raw.x));
                        float2 s1v = __half22float2(u2h(raw.y));
                        float2 s2v = __half22float2(u2h(raw.z));
                        float2 s3v = __half22float2(u2h(raw.w));
                        o8[0] += s0v.x*vn; o8[1] += s0v.y*vn;
                        o8[2] += s1v.x*vn; o8[3] += s1v.y*vn;
                        o8[4] += s2v.x*vn; o8[5] += s2v.y*vn;
                        o8[6] += s3v.x*vn; o8[7] += s3v.y*vn;
                    }
                    if (s >= s0 && s < s0 + 8 &&
                        hh >= 1 && hh <= 8 && ww >= 1 && ww <= 32) {
                        #pragma unroll
                        for (int g = 0; g < 8; g++)
                            out_sim[((size_t)(b*8 + g)*Dc + s)*HWc + pix] = o8[g];
                    }
                }
                #pragma unroll
                for (int g = 0; g < 8; g++)
                    xs[g*360 + pos] = o8[g];
            }
        }
        __syncthreads();
        if (have) {
            #pragma unroll 1
            for (int i = 0; i < 8; i++) {
                #pragma unroll
                for (int kh = 0; kh < 3; kh++) {
                    const float2* row = (const float2*)&xs[(i*10 + gy + kh)*36 + gx*8];
                    float2 q0 = row[0], q1 = row[1], q2 = row[2], q3 = row[3], q4 = row[4];
                    unsigned long long P0 = pk2(q0.x, q0.y);
                    unsigned long long P1 = pk2(q1.x, q1.y);
                    unsigned long long P2 = pk2(q2.x, q2.y);
                    unsigned long long P3 = pk2(q3.x, q3.y);
                    unsigned long long P4 = pk2(q4.x, q4.y);
                    unsigned long long M0 = pk2(q0.y, q1.x);
                    unsigned long long M1 = pk2(q1.y, q2.x);
                    unsigned long long M2 = pk2(q2.y, q3.x);
                    unsigned long long M3 = pk2(q3.y, q4.x);
                    const unsigned long long* wb = &wsp[(i*3 + kh)*72 + (2*og)*9];
                    #pragma unroll
                    for (int o2 = 0; o2 < 2; o2++) {
                        const unsigned long long* wo = wb + o2*9;
                        #pragma unroll
                        for (int kd = 0; kd < 3; kd++) {
                            unsigned long long wk0 = wo[kd*3+0];
                            unsigned long long wk1 = wo[kd*3+1];
                            unsigned long long wk2 = wo[kd*3+2];
                            unsigned long long* ap = &acc[2-kd][o2*4];
                            fma2(ap[0], wk0, P0); fma2(ap[1], wk0, P1);
                            fma2(ap[2], wk0, P2); fma2(ap[3], wk0, P3);
                            fma2(ap[0], wk1, M0); fma2(ap[1], wk1, M1);
                            fma2(ap[2], wk1, M2); fma2(ap[3], wk1, M3);
                            fma2(ap[0], wk2, P1); fma2(ap[1], wk2, P2);
                            fma2(ap[2], wk2, P3); fma2(ap[3], wk2, P4);
                        }
                    }
                }
            }
        }
        int so = s - 1;
        if (so >= s0 && so < s0 + 8) {
            size_t pb = (size_t)so*HWc + (h0+gy)*Wc + (w0 + gx*8);
            #pragma unroll
            for (int o2 = 0; o2 < 2; o2++) {
                int o = 2*og + o2;
                float bb = bsm[o];
                float2 r0 = upk2(acc[0][o2*4+0]);
                float2 r1 = upk2(acc[0][o2*4+1]);
                float2 r2 = upk2(acc[0][o2*4+2]);
                float2 r3 = upk2(acc[0][o2*4+3]);
                float4 ovA = make_float4(fmaxf(r0.x+bb,0.f), fmaxf(r0.y+bb,0.f),
                                         fmaxf(r1.x+bb,0.f), fmaxf(r1.y+bb,0.f));
                float4 ovB = make_float4(fmaxf(r2.x+bb,0.f), fmaxf(r2.y+bb,0.f),
                                         fmaxf(r3.x+bb,0.f), fmaxf(r3.y+bb,0.f));
                *(float4*)&outb[(size_t)o*Dc*HWc + pb]     = ovA;
                *(float4*)&outb[(size_t)o*Dc*HWc + pb + 4] = ovB;
            }
        }
        #pragma unroll
        for (int k = 0; k < 8; k++) {
            acc[0][k] = acc[1][k];
            acc[1][k] = acc[2][k];
            acc[2][k] = 0ull;
        }
    }
}

// ---------------- conv3d 8->1, 3x3x3, pad 1 (unchanged) --------------------
#define TW 32
#define TH 16
#define DCH 8
__global__ void __launch_bounds__(128) conv2_kernel(const float* __restrict__ w2,
                                                    const float* __restrict__ b2,
                                                    float* __restrict__ out_pvp) {
    __shared__ float  xs[8*18*34];
    __shared__ float4 wsm[8*3*3];
    __shared__ float  bias;
    int tid = threadIdx.x;
    int tx = tid & 7, ty = tid >> 3;
    int w0 = blockIdx.x * TW, h0 = blockIdx.y * TH;
    int b = blockIdx.z >> 2, s0 = (blockIdx.z & 3) * DCH;
    int lx = tx * 4;

    for (int idx = tid; idx < 8*3*3; idx += 128) {
        int i = idx / 9, r = idx % 9;
        int kh = r / 3, kd = r % 3;
        const float* wp = w2 + i*27 + kd*9 + kh*3;
        wsm[idx] = make_float4(wp[0], wp[1], wp[2], 0.f);
    }
    if (tid == 0) bias = b2[0];

    const float* base = g_c1 + (size_t)b*8*Dc*HWc;

    unsigned long long aP[2], aC[2], aN[2];
    aP[0]=aP[1]=aC[0]=aC[1]=aN[0]=aN[1]=0ull;

    #pragma unroll 1
    for (int s = s0-1; s <= s0+DCH; s++) {
        bool have = (s >= 0 && s < Dc);
        __syncthreads();
        if (have) {
            for (int idx = tid; idx < 8*18*34; idx += 128) {
                int i = idx / (18*34), r = idx % (18*34);
                int hh = r / 34, ww = r % 34;
                int gh = h0 + hh - 1, gw = w0 + ww - 1;
                float val = 0.0f;
                if ((unsigned)gh < (unsigned)Hc && (unsigned)gw < (unsigned)Wc)
                    val = base[((size_t)i*Dc + s)*HWc + gh*Wc + gw];
                xs[idx] = val;
            }
        }
        __syncthreads();
        if (have) {
            #pragma unroll 1
            for (int i = 0; i < 8; i++) {
                #pragma unroll
                for (int kh = 0; kh < 3; kh++) {
                    const float* row = &xs[(i*18 + ty + kh)*34 + lx];
                    float2 q0 = *(const float2*)(row);
                    float2 q1 = *(const float2*)(row+2);
                    float2 q2 = *(const float2*)(row+4);
                    unsigned long long A0 = pk2(q0.x, q0.y);
                    unsigned long long B0 = pk2(q1.x, q1.y);
                    unsigned long long A1 = pk2(q0.y, q1.x);
                    unsigned long long B1 = pk2(q1.y, q2.x);
                    unsigned long long C0 = pk2(q2.x, q2.y);
                    float4 wn = wsm[(i*3+kh)*3+0];
                    float4 wc = wsm[(i*3+kh)*3+1];
                    float4 wv = wsm[(i*3+kh)*3+2];
                    unsigned long long t;
                    t = pk2(wn.x,wn.x); fma2(aN[0],t,A0); fma2(aN[1],t,B0);
                    t = pk2(wn.y,wn.y); fma2(aN[0],t,A1); fma2(aN[1],t,B1);
                    t = pk2(wn.z,wn.z); fma2(aN[0],t,B0); fma2(aN[1],t,C0);
                    t = pk2(wc.x,wc.x); fma2(aC[0],t,A0); fma2(aC[1],t,B0);
                    t = pk2(wc.y,wc.y); fma2(aC[0],t,A1); fma2(aC[1],t,B1);
                    t = pk2(wc.z,wc.z); fma2(aC[0],t,B0); fma2(aC[1],t,C0);
                    t = pk2(wv.x,wv.x); fma2(aP[0],t,A0); fma2(aP[1],t,B0);
                    t = pk2(wv.y,wv.y); fma2(aP[0],t,A1); fma2(aP[1],t,B1);
                    t = pk2(wv.z,wv.z); fma2(aP[0],t,B0); fma2(aP[1],t,C0);
                }
            }
        }
        int so = s - 1;
        if (so >= s0 && so < s0 + DCH) {
            float2 pA = upk2(aP[0]), pB = upk2(aP[1]);
            float4 ov = make_float4(pA.x+bias, pA.y+bias, pB.x+bias, pB.y+bias);
            *(float4*)&out_pvp[((size_t)b*Dc + so)*HWc + (h0+ty)*Wc + (w0+lx)] = ov;
        }
        aP[0]=aC[0]; aP[1]=aC[1]; aC[0]=aN[0]; aC[1]=aN[1]; aN[0]=0ull; aN[1]=0ull;
    }
}

// ---------------- depth softmax + expectation + confidence -----------------
__global__ void final_kernel(const float* __restrict__ pvp,
                             const float* __restrict__ dv,
                             float* __restrict__ depth_out,
                             float* __restrict__ conf_out) {
    int p = blockIdx.x * blockDim.x + threadIdx.x;
    if (p >= BHW) return;
    int b = p / HWc, pix = p % HWc;
    const float* vp  = pvp + (size_t)b*Dc*HWc + pix;
    const float* dvp = dv  + (size_t)b*Dc*HWc + pix;

    float x[Dc];
    float m = -1e30f;
    #pragma unroll
    for (int d = 0; d < Dc; d++) { x[d] = vp[(size_t)d*HWc]; m = fmaxf(m, x[d]); }
    float s = 0.0f;
    #pragma unroll
    for (int d = 0; d < Dc; d++) { x[d] = __expf(x[d] - m); s += x[d]; }
    float inv_s = 1.0f / s;
    float depth = 0.0f, dif = 0.0f;
    #pragma unroll
    for (int d = 0; d < Dc; d++) {
        float pd = x[d] * inv_s;
        x[d] = pd;
        depth += pd * dvp[(size_t)d*HWc];
        dif += pd * (float)d;
    }
    int di = min(max((int)dif, 0), Dc-1);
    float c4 = 0.0f;
    #pragma unroll
    for (int d = 0; d < Dc; d++) {
        bool in = (d >= di - 1) && (d <= di + 2);
        c4 += in ? x[d] : 0.0f;
    }
    depth_out[p] = depth;
    conf_out[p] = c4;
}

// ---------------- launch ----------------------------------------------------
extern "C" void kernel_launch(void* const* d_in, const int* in_sizes, int n_in,
                              void* d_out, int out_size) {
    const float* features = (const float*)d_in[0];
    const float* pm       = (const float*)d_in[1];
    const float* dv       = (const float*)d_in[2];
    const float* rw1      = (const float*)d_in[3];
    const float* rb1      = (const float*)d_in[4];
    const float* rw2      = (const float*)d_in[5];
    const float* rb2      = (const float*)d_in[6];
    const float* pw1      = (const float*)d_in[7];
    const float* pb1      = (const float*)d_in[8];
    const float* pw2      = (const float*)d_in[9];
    const float* pb2      = (const float*)d_in[10];
    const float* pw3      = (const float*)d_in[11];
    const float* pb3      = (const float*)d_in[12];

    float* out       = (float*)d_out;
    float* out_depth = out;
    float* out_conf  = out + BHW;
    float* out_vw    = out + 2*BHW;
    float* out_pvp   = out + 2*BHW + (Vc-1)*BHW;
    float* out_sim   = out_pvp + BDHW;

    proj_kernel<<<1, 32>>>(pm, dv, pw1, pb1, pw2, pb2, pw3, pb3);       // 1

    {
        dim3 grd(HWc/32, Vc*Bc);
        transpose_kernel<<<grd, 256>>>(features, dv);                   // 2
    }
    {
        dim3 grd(HWc/256, Bc, Vc-1);
        warp_sim_kernel<<<grd, 512>>>(dv, pw1, pb1, pw2, pb2, pw3, pb3, out_vw);  // 3
    }
    {
        dim3 grd1(Wc/32, Hc/8, Bc*4);
        conv1_kernel<<<grd1, 128>>>(out_vw, rw1, rb1, out_sim);         // 4 <- profiled
        dim3 grd2(Wc/TW, Hc/TH, Bc*(Dc/DCH));
        conv2_kernel<<<grd2, 128>>>(rw2, rb2, out_pvp);                 // 5
    }

    final_kernel<<<(BHW + 255)/256, 256>>>(out_pvp, dv, out_depth, out_conf);  // 6
}